// round 6
// baseline (speedup 1.0000x reference)
#include <cuda_runtime.h>
#include <math.h>

#define NPROP 1500
#define NACT 64
#define NCLS 81
#define PERSON_IDX 2
#define O_CHUNK 750          // 1500 / 2 chunks -> only 3000 blocks / 3000 prologues
#define THREADS 512
#define TILE_F4 ((O_CHUNK * NACT) / 4)   // 12000 float4 per block tile

// out[h, o, a] = H[h]*O[o]*L[h,a]*exp(-|enc-mu|^2 * k)
//             = O[o] * (H*L*exp(-k*|mu|^2))[a] * exp( dot(enc, 2k*mu[a]) - k*|enc|^2 )
//
// Grid (2, 1500): each block owns [h, 750 o's, 64 a's] = 192 KB of output, so
// the argmax prologue runs 3000x instead of 22500x — its cost amortizes to
// ~0.4us. Zero path (98.8%) is a pure unconditional float4 stream.
__global__ void __launch_bounds__(THREADS, 4)
score_kernel(const float* __restrict__ action_logits,
             const float* __restrict__ target_mean,
             const float* __restrict__ bbox,
             const float* __restrict__ scores,
             float* __restrict__ out) {
    const int h    = blockIdx.y;
    const int o0   = blockIdx.x * O_CHUNK;
    const int tid  = threadIdx.x;
    const int lane = tid & 31;

    __shared__ float sH;

    // warp 0: scores argmax (first-index tie-break, matches jnp.argmax)
    if (tid < 32) {
        const float* srow = scores + (size_t)h * NCLS;
        float best = srow[lane];
        int   bi   = lane;
        float v1 = srow[lane + 32];
        if (v1 > best) { best = v1; bi = lane + 32; }
        if (lane + 64 < NCLS) {
            float v2 = srow[lane + 64];
            if (v2 > best) { best = v2; bi = lane + 64; }
        }
        #pragma unroll
        for (int s = 16; s > 0; s >>= 1) {
            float ov = __shfl_xor_sync(0xffffffffu, best, s);
            int   oi = __shfl_xor_sync(0xffffffffu, bi, s);
            if (ov > best || (ov == best && oi < bi)) { best = ov; bi = oi; }
        }
        if (lane == 0) sH = (bi == PERSON_IDX) ? best : 0.0f;
    }
    __syncthreads();

    const float H = sH;
    float* blk_out = out + (size_t)h * (NPROP * NACT) + (size_t)o0 * NACT;

    if (H == 0.0f) {
        // pure zero-fill: 12000 float4 = 192 KB streaming STG.128
        const float4 z = make_float4(0.f, 0.f, 0.f, 0.f);
        float4* p = reinterpret_cast<float4*>(blk_out);
        #pragma unroll 4
        for (int i = tid; i < TILE_F4; i += THREADS)
            p[i] = z;
        return;
    }

    // ---- rare person path (~1.2% of blocks) ----
    const float K = 5.5555555555555554f;  // 1/(2*0.3^2)

    __shared__ float sM0[NACT], sM1[NACT], sM2[NACT], sM3[NACT], sHQ[NACT];
    __shared__ float sOv[O_CHUNK], sOcx[O_CHUNK], sOcy[O_CHUNK];
    __shared__ float sOlw[O_CHUNK], sOlh[O_CHUNK];

    if (tid < NACT) {
        const float* mu = target_mean + ((size_t)h * NACT + tid) * 4;
        float m0 = mu[0], m1 = mu[1], m2 = mu[2], m3 = mu[3];
        float msq = m0 * m0 + m1 * m1 + m2 * m2 + m3 * m3;
        float twoK = 2.0f * K;
        sM0[tid] = twoK * m0;
        sM1[tid] = twoK * m1;
        sM2[tid] = twoK * m2;
        sM3[tid] = twoK * m3;
        sHQ[tid] = H * action_logits[(size_t)h * NACT + tid] * __expf(-K * msq);
    }

    // per-o stats into shared (serial 81-class argmax each; L2-hit)
    for (int j = tid; j < O_CHUNK; j += THREADS) {
        int o = o0 + j;
        const float* s = scores + (size_t)o * NCLS;
        float ob = s[0];
        int oidx = 0;
        #pragma unroll 8
        for (int c = 1; c < NCLS; c++) {
            float v = s[c];
            if (v > ob) { ob = v; oidx = c; }
        }
        sOv[j] = (oidx == PERSON_IDX) ? 0.0f : ob;

        float x0 = bbox[o * 4 + 0], y0 = bbox[o * 4 + 1];
        float x1 = bbox[o * 4 + 2], y1 = bbox[o * 4 + 3];
        float w = x1 - x0, hh = y1 - y0;
        sOcx[j] = x0 + 0.5f * w;
        sOcy[j] = y0 + 0.5f * hh;
        sOlw[j] = logf(w);
        sOlh[j] = logf(hh);
    }

    // h box stats (broadcast loads, every thread)
    float hx0 = bbox[h * 4 + 0], hy0 = bbox[h * 4 + 1];
    float hx1 = bbox[h * 4 + 2], hy1 = bbox[h * 4 + 3];
    float hw = hx1 - hx0, hhh = hy1 - hy0;
    const float cxh = hx0 + 0.5f * hw;
    const float cyh = hy0 + 0.5f * hhh;
    const float iw = 1.0f / hw, ih = 1.0f / hhh;
    const float lw = logf(hw), lh = logf(hhh);

    __syncthreads();   // publish smem staging

    const int a    = tid & (NACT - 1);
    const int osub = tid >> 6;              // 0..7
    const float M0 = sM0[a], M1 = sM1[a], M2 = sM2[a], M3 = sM3[a];
    const float HQ = sHQ[a];

    for (int j = osub; j < O_CHUNK; j += (THREADS / NACT)) {
        float Ov = sOv[j];
        float tx = (sOcx[j] - cxh) * iw;
        float ty = (sOcy[j] - cyh) * ih;
        float tw = sOlw[j] - lw;
        float th = sOlh[j] - lh;
        float e2 = tx * tx + ty * ty + tw * tw + th * th;
        float ex = fmaf(tx, M0, fmaf(ty, M1, fmaf(tw, M2, th * M3))) - K * e2;
        blk_out[(size_t)j * NACT + a] = Ov * HQ * __expf(ex);
    }
}

extern "C" void kernel_launch(void* const* d_in, const int* in_sizes, int n_in,
                              void* d_out, int out_size) {
    const float* action_logits = (const float*)d_in[0];  // [1500,64]
    const float* target_mean   = (const float*)d_in[1];  // [1500,64,4]
    const float* bbox          = (const float*)d_in[2];  // [1500,4]
    const float* scores        = (const float*)d_in[3];  // [1500,81]
    float* out = (float*)d_out;                          // [1500,1500,64]

    dim3 grid(NPROP / O_CHUNK, NPROP);  // (2, 1500)
    score_kernel<<<grid, THREADS>>>(action_logits, target_mean, bbox, scores, out);
}

// round 7
// speedup vs baseline: 1.0291x; 1.0291x over previous
#include <cuda_runtime.h>
#include <math.h>

#define NPROP 1500
#define NACT 64
#define NCLS 81
#define PERSON_IDX 2
#define O_CHUNK 100
#define NTILES_X 15                       // 1500 / O_CHUNK
#define NTILES (NPROP * NTILES_X)         // 22500
#define THREADS 256
#define TILE_F4 ((O_CHUNK * NACT) / 4)    // 1600 float4 per tile
#define NBLOCKS 1216                      // ~SMs * occ8, persistent

// out[h, o, a] = H[h]*O[o]*L[h,a]*exp(-|enc-mu|^2 * k)
//             = O[o] * (H*L*exp(-k*|mu|^2))[a] * exp( dot(enc, 2k*mu[a]) - k*|enc|^2 )
//
// Persistent blocks grid-stride over tiles. The scores row for tile t+stride
// is loaded while tile t's stores drain, so the argmax prologue latency is
// hidden everywhere except each block's first tile.
__global__ void __launch_bounds__(THREADS, 8)
score_kernel(const float* __restrict__ action_logits,
             const float* __restrict__ target_mean,
             const float* __restrict__ bbox,
             const float* __restrict__ scores,
             float* __restrict__ out) {
    const int tid  = threadIdx.x;
    const int lane = tid & 31;
    const int stride = gridDim.x;

    __shared__ float sM0[NACT], sM1[NACT], sM2[NACT], sM3[NACT], sHQ[NACT];
    __shared__ float sOv[O_CHUNK], sOcx[O_CHUNK], sOcy[O_CHUNK];
    __shared__ float sOlw[O_CHUNK], sOlh[O_CHUNK];

    int t = blockIdx.x;
    if (t >= NTILES) return;

    // prefetch scores row for first tile (per-warp, redundant across warps)
    float v0, v1, v2;
    {
        const float* srow = scores + (size_t)(t / NTILES_X) * NCLS;
        v0 = srow[lane];
        v1 = srow[lane + 32];
        v2 = (lane + 64 < NCLS) ? srow[lane + 64] : -INFINITY;
    }

    while (t < NTILES) {
        const int tn = t + stride;

        // resolve current tile's argmax (loads issued one tile ago)
        float best = v0;
        int   bi   = lane;
        if (v1 > best) { best = v1; bi = lane + 32; }
        if (v2 > best) { best = v2; bi = lane + 64; }
        #pragma unroll
        for (int s = 16; s > 0; s >>= 1) {
            float ov = __shfl_xor_sync(0xffffffffu, best, s);
            int   oi = __shfl_xor_sync(0xffffffffu, bi, s);
            if (ov > best || (ov == best && oi < bi)) { best = ov; bi = oi; }
        }
        const float H = (bi == PERSON_IDX) ? best : 0.0f;

        // prefetch next tile's scores row (in flight during the store loop)
        if (tn < NTILES) {
            const float* srow = scores + (size_t)(tn / NTILES_X) * NCLS;
            v0 = srow[lane];
            v1 = srow[lane + 32];
            v2 = (lane + 64 < NCLS) ? srow[lane + 64] : -INFINITY;
        }

        const int h  = t / NTILES_X;
        const int o0 = (t - h * NTILES_X) * O_CHUNK;
        float* blk_out = out + (size_t)h * (NPROP * NACT) + (size_t)o0 * NACT;

        if (H == 0.0f) {
            // 98.8% of tiles: pure zero stream
            const float4 z = make_float4(0.f, 0.f, 0.f, 0.f);
            float4* p = reinterpret_cast<float4*>(blk_out);
            #pragma unroll 4
            for (int i = tid; i < TILE_F4; i += THREADS)
                p[i] = z;
        } else {
            // ---- rare person tile (~1.2%) ----
            const float K = 5.5555555555555554f;  // 1/(2*0.3^2)

            if (tid < NACT) {
                const float* mu = target_mean + ((size_t)h * NACT + tid) * 4;
                float m0 = mu[0], m1 = mu[1], m2 = mu[2], m3 = mu[3];
                float msq = m0 * m0 + m1 * m1 + m2 * m2 + m3 * m3;
                float twoK = 2.0f * K;
                sM0[tid] = twoK * m0;
                sM1[tid] = twoK * m1;
                sM2[tid] = twoK * m2;
                sM3[tid] = twoK * m3;
                sHQ[tid] = H * action_logits[(size_t)h * NACT + tid] * __expf(-K * msq);
            }

            for (int j = tid; j < O_CHUNK; j += THREADS) {
                int o = o0 + j;
                const float* s = scores + (size_t)o * NCLS;
                float ob = s[0];
                int oidx = 0;
                #pragma unroll 8
                for (int c = 1; c < NCLS; c++) {
                    float v = s[c];
                    if (v > ob) { ob = v; oidx = c; }
                }
                sOv[j] = (oidx == PERSON_IDX) ? 0.0f : ob;

                float x0 = bbox[o * 4 + 0], y0 = bbox[o * 4 + 1];
                float x1 = bbox[o * 4 + 2], y1 = bbox[o * 4 + 3];
                float w = x1 - x0, hh = y1 - y0;
                sOcx[j] = x0 + 0.5f * w;
                sOcy[j] = y0 + 0.5f * hh;
                sOlw[j] = logf(w);
                sOlh[j] = logf(hh);
            }

            float hx0 = bbox[h * 4 + 0], hy0 = bbox[h * 4 + 1];
            float hx1 = bbox[h * 4 + 2], hy1 = bbox[h * 4 + 3];
            float hw = hx1 - hx0, hhh = hy1 - hy0;
            const float cxh = hx0 + 0.5f * hw;
            const float cyh = hy0 + 0.5f * hhh;
            const float iw = 1.0f / hw, ih = 1.0f / hhh;
            const float lw = logf(hw), lh = logf(hhh);

            __syncthreads();   // publish staging

            const int a    = tid & (NACT - 1);
            const int osub = tid >> 6;          // 0..3
            const float M0 = sM0[a], M1 = sM1[a], M2 = sM2[a], M3 = sM3[a];
            const float HQ = sHQ[a];

            for (int j = osub; j < O_CHUNK; j += (THREADS / NACT)) {
                float Ov = sOv[j];
                float tx = (sOcx[j] - cxh) * iw;
                float ty = (sOcy[j] - cyh) * ih;
                float tw = sOlw[j] - lw;
                float th = sOlh[j] - lh;
                float e2 = tx * tx + ty * ty + tw * tw + th * th;
                float ex = fmaf(tx, M0, fmaf(ty, M1, fmaf(tw, M2, th * M3))) - K * e2;
                blk_out[(size_t)j * NACT + a] = Ov * HQ * __expf(ex);
            }

            __syncthreads();   // protect staging from the next person tile
        }

        t = tn;
    }
}

extern "C" void kernel_launch(void* const* d_in, const int* in_sizes, int n_in,
                              void* d_out, int out_size) {
    const float* action_logits = (const float*)d_in[0];  // [1500,64]
    const float* target_mean   = (const float*)d_in[1];  // [1500,64,4]
    const float* bbox          = (const float*)d_in[2];  // [1500,4]
    const float* scores        = (const float*)d_in[3];  // [1500,81]
    float* out = (float*)d_out;                          // [1500,1500,64]

    score_kernel<<<NBLOCKS, THREADS>>>(action_logits, target_mean, bbox, scores, out);
}

// round 8
// speedup vs baseline: 1.2524x; 1.2171x over previous
#include <cuda_runtime.h>
#include <math.h>

#define NPROP 1500
#define NACT 64
#define NCLS 81
#define PERSON_IDX 2
#define O_CHUNK 50           // 1500 / 30 chunks: halves person-tile MUFU dwell
#define THREADS 256
#define TILE_F4 ((O_CHUNK * NACT) / 4)   // 800 float4 per block tile

// out[h, o, a] = H[h]*O[o]*L[h,a]*exp(-|enc-mu|^2 * k)
//             = O[o] * (H*L*exp(-k*|mu|^2))[a] * exp( dot(enc, 2k*mu[a]) - k*|enc|^2 )
//
// O_CHUNK=50: a person tile is only 3200 MUFU-EX2 (~3.2us dwell vs 6.4us at
// 100), so late-scheduled person tiles extend the kernel tail less, and each
// person (h,chunk)'s work spreads across 2x the SMs.
__global__ void __launch_bounds__(THREADS, 8)
score_kernel(const float* __restrict__ action_logits,
             const float* __restrict__ target_mean,
             const float* __restrict__ bbox,
             const float* __restrict__ scores,
             float* __restrict__ out) {
    const int h    = blockIdx.y;
    const int o0   = blockIdx.x * O_CHUNK;
    const int tid  = threadIdx.x;
    const int lane = tid & 31;

    __shared__ float sH;

    // warp 0: scores argmax (first-index tie-break, matches jnp.argmax)
    if (tid < 32) {
        const float* srow = scores + (size_t)h * NCLS;
        float best = srow[lane];
        int   bi   = lane;
        float v1 = srow[lane + 32];
        if (v1 > best) { best = v1; bi = lane + 32; }
        if (lane + 64 < NCLS) {
            float v2 = srow[lane + 64];
            if (v2 > best) { best = v2; bi = lane + 64; }
        }
        #pragma unroll
        for (int s = 16; s > 0; s >>= 1) {
            float ov = __shfl_xor_sync(0xffffffffu, best, s);
            int   oi = __shfl_xor_sync(0xffffffffu, bi, s);
            if (ov > best || (ov == best && oi < bi)) { best = ov; bi = oi; }
        }
        if (lane == 0) sH = (bi == PERSON_IDX) ? best : 0.0f;
    }
    __syncthreads();

    const float H = sH;
    float* blk_out = out + (size_t)h * (NPROP * NACT) + (size_t)o0 * NACT;

    if (H == 0.0f) {
        // 98.8% of blocks: pure contiguous zero stream (12.8 KB)
        const float4 z = make_float4(0.f, 0.f, 0.f, 0.f);
        float4* p = reinterpret_cast<float4*>(blk_out);
        #pragma unroll 4
        for (int i = tid; i < TILE_F4; i += THREADS)
            p[i] = z;
        return;
    }

    // ---- rare person path (~1.2% of blocks) ----
    const float K = 5.5555555555555554f;  // 1/(2*0.3^2)

    __shared__ float sM0[NACT], sM1[NACT], sM2[NACT], sM3[NACT], sHQ[NACT];
    __shared__ float sOv[O_CHUNK], sOcx[O_CHUNK], sOcy[O_CHUNK];
    __shared__ float sOlw[O_CHUNK], sOlh[O_CHUNK];

    if (tid < NACT) {
        const float* mu = target_mean + ((size_t)h * NACT + tid) * 4;
        float m0 = mu[0], m1 = mu[1], m2 = mu[2], m3 = mu[3];
        float msq = m0 * m0 + m1 * m1 + m2 * m2 + m3 * m3;
        float twoK = 2.0f * K;
        sM0[tid] = twoK * m0;
        sM1[tid] = twoK * m1;
        sM2[tid] = twoK * m2;
        sM3[tid] = twoK * m3;
        sHQ[tid] = H * action_logits[(size_t)h * NACT + tid] * __expf(-K * msq);
    }

    // per-o stats into shared (serial 81-class argmax each; L2-hit)
    for (int j = tid; j < O_CHUNK; j += THREADS) {
        int o = o0 + j;
        const float* s = scores + (size_t)o * NCLS;
        float ob = s[0];
        int oidx = 0;
        #pragma unroll 8
        for (int c = 1; c < NCLS; c++) {
            float v = s[c];
            if (v > ob) { ob = v; oidx = c; }
        }
        sOv[j] = (oidx == PERSON_IDX) ? 0.0f : ob;

        float x0 = bbox[o * 4 + 0], y0 = bbox[o * 4 + 1];
        float x1 = bbox[o * 4 + 2], y1 = bbox[o * 4 + 3];
        float w = x1 - x0, hh = y1 - y0;
        sOcx[j] = x0 + 0.5f * w;
        sOcy[j] = y0 + 0.5f * hh;
        sOlw[j] = logf(w);
        sOlh[j] = logf(hh);
    }

    // h box stats (broadcast loads, every thread)
    float hx0 = bbox[h * 4 + 0], hy0 = bbox[h * 4 + 1];
    float hx1 = bbox[h * 4 + 2], hy1 = bbox[h * 4 + 3];
    float hw = hx1 - hx0, hhh = hy1 - hy0;
    const float cxh = hx0 + 0.5f * hw;
    const float cyh = hy0 + 0.5f * hhh;
    const float iw = 1.0f / hw, ih = 1.0f / hhh;
    const float lw = logf(hw), lh = logf(hhh);

    __syncthreads();   // publish smem staging

    const int a    = tid & (NACT - 1);
    const int osub = tid >> 6;              // 0..3
    const float M0 = sM0[a], M1 = sM1[a], M2 = sM2[a], M3 = sM3[a];
    const float HQ = sHQ[a];

    for (int j = osub; j < O_CHUNK; j += (THREADS / NACT)) {
        float Ov = sOv[j];
        float tx = (sOcx[j] - cxh) * iw;
        float ty = (sOcy[j] - cyh) * ih;
        float tw = sOlw[j] - lw;
        float th = sOlh[j] - lh;
        float e2 = tx * tx + ty * ty + tw * tw + th * th;
        float ex = fmaf(tx, M0, fmaf(ty, M1, fmaf(tw, M2, th * M3))) - K * e2;
        blk_out[(size_t)j * NACT + a] = Ov * HQ * __expf(ex);
    }
}

extern "C" void kernel_launch(void* const* d_in, const int* in_sizes, int n_in,
                              void* d_out, int out_size) {
    const float* action_logits = (const float*)d_in[0];  // [1500,64]
    const float* target_mean   = (const float*)d_in[1];  // [1500,64,4]
    const float* bbox          = (const float*)d_in[2];  // [1500,4]
    const float* scores        = (const float*)d_in[3];  // [1500,81]
    float* out = (float*)d_out;                          // [1500,1500,64]

    dim3 grid(NPROP / O_CHUNK, NPROP);  // (30, 1500)
    score_kernel<<<grid, THREADS>>>(action_logits, target_mean, bbox, scores, out);
}